// round 2
// baseline (speedup 1.0000x reference)
#include <cuda_runtime.h>
#include <cuda_bf16.h>
#include <cstdint>

#define N_NODES 50000
#define N_EDGES 800000
#define N_GRAPHS 1024
#define H 128
#define H2 256
#define L 5

// ---------------- scratch (__device__ globals: allowed) ----------------
__device__ float          g_x[N_NODES * H];
__device__ __nv_bfloat16  g_x_bf[N_NODES * H];
__device__ __nv_bfloat16  g_e_bf[(size_t)N_EDGES * H];
__device__ __nv_bfloat16  g_h1[(size_t)N_EDGES * H2];
__device__ float          g_aggr[N_NODES * H];
__device__ float          g_cnt[N_NODES];
__device__ float          g_crystal[N_GRAPHS * H];
__device__ float          g_gcnt[N_GRAPHS];
__device__ __nv_bfloat16  g_w1[L * H2 * H2];
__device__ __nv_bfloat16  g_w2[L * H2 * H];

__device__ __forceinline__ float silu(float x) { return x / (1.f + expf(-x)); }

// ---------------- PTX helpers ----------------
__device__ __forceinline__ void ldsm_x4(uint32_t r[4], const void* p) {
    uint32_t a = (uint32_t)__cvta_generic_to_shared(p);
    asm volatile("ldmatrix.sync.aligned.m8n8.x4.shared.b16 {%0,%1,%2,%3},[%4];\n"
                 : "=r"(r[0]), "=r"(r[1]), "=r"(r[2]), "=r"(r[3]) : "r"(a));
}
__device__ __forceinline__ void ldsm_x4t(uint32_t r[4], const void* p) {
    uint32_t a = (uint32_t)__cvta_generic_to_shared(p);
    asm volatile("ldmatrix.sync.aligned.m8n8.x4.trans.shared.b16 {%0,%1,%2,%3},[%4];\n"
                 : "=r"(r[0]), "=r"(r[1]), "=r"(r[2]), "=r"(r[3]) : "r"(a));
}
__device__ __forceinline__ void mma_bf16(float d[4], const uint32_t a[4], uint32_t b0, uint32_t b1) {
    asm volatile(
        "mma.sync.aligned.m16n8k16.row.col.f32.bf16.bf16.f32 "
        "{%0,%1,%2,%3},{%4,%5,%6,%7},{%8,%9},{%0,%1,%2,%3};\n"
        : "+f"(d[0]), "+f"(d[1]), "+f"(d[2]), "+f"(d[3])
        : "r"(a[0]), "r"(a[1]), "r"(a[2]), "r"(a[3]), "r"(b0), "r"(b1));
}
__device__ __forceinline__ void red_v2(float* p, float a, float b) {
    asm volatile("red.global.add.v2.f32 [%0], {%1,%2};\n" :: "l"(p), "f"(a), "f"(b) : "memory");
}

// ---------------- small kernels ----------------
__global__ void zero_kernel() {
    int i = blockIdx.x * 256 + threadIdx.x;
    if (i < N_NODES * H)  g_aggr[i] = 0.f;
    if (i < N_NODES)      g_cnt[i] = 0.f;
    if (i < N_GRAPHS * H) g_crystal[i] = 0.f;
    if (i < N_GRAPHS)     g_gcnt[i] = 0.f;
}

__global__ void prep_w(const float* w1, const float* w2) {
    int i = blockIdx.x * 256 + threadIdx.x;
    if (i < L * H2 * H2) g_w1[i] = __float2bfloat16(w1[i]);
    if (i < L * H2 * H)  g_w2[i] = __float2bfloat16(w2[i]);
}

__device__ __forceinline__ void ln_stats(float v, float& mean, float& var) {
    __shared__ float red[8];
    int lane = threadIdx.x & 31, wid = threadIdx.x >> 5;
    float s = v;
    #pragma unroll
    for (int o = 16; o; o >>= 1) s += __shfl_xor_sync(0xffffffffu, s, o);
    if (!lane) red[wid] = s;
    __syncthreads();
    mean = (red[0] + red[1] + red[2] + red[3]) * (1.f / H);
    float d = v - mean, sq = d * d;
    #pragma unroll
    for (int o = 16; o; o >>= 1) sq += __shfl_xor_sync(0xffffffffu, sq, o);
    if (!lane) red[4 + wid] = sq;
    __syncthreads();
    var = (red[4] + red[5] + red[6] + red[7]) * (1.f / H);
}

__global__ __launch_bounds__(H) void node_embed(const float* atom, const float* w,
                                                const float* b, const float* lg, const float* lb) {
    int n = blockIdx.x, c = threadIdx.x;
    float a0 = atom[n * 4 + 0], a1 = atom[n * 4 + 1], a2 = atom[n * 4 + 2], a3 = atom[n * 4 + 3];
    float v = b[c] + a0 * w[c] + a1 * w[H + c] + a2 * w[2 * H + c] + a3 * w[3 * H + c];
    float mean, var;
    ln_stats(v, mean, var);
    float y = (v - mean) * rsqrtf(var + 1e-5f) * lg[c] + lb[c];
    y = silu(y);
    g_x[n * H + c] = y;
    g_x_bf[n * H + c] = __float2bfloat16(y);
}

__global__ __launch_bounds__(256) void edge_embed(const float* nf, const float* w, const float* b) {
    __shared__ float ws[41 * H];
    __shared__ float bs[H];
    __shared__ float nfs[64 * 41];
    int tid = threadIdx.x;
    int e0 = blockIdx.x * 64;
    for (int i = tid; i < 41 * H; i += 256) ws[i] = w[i];
    if (tid < H) bs[tid] = b[tid];
    for (int i = tid; i < 64 * 41; i += 256) nfs[i] = nf[e0 * 41 + i];
    __syncthreads();
    for (int i = tid; i < 64 * H; i += 256) {
        int e = i >> 7, c = i & 127;
        float a = bs[c];
        #pragma unroll
        for (int k = 0; k < 41; k++) a += nfs[e * 41 + k] * ws[k * H + c];
        g_e_bf[(size_t)(e0 + e) * H + c] = __float2bfloat16(silu(a));
    }
}

__global__ void cnt_kernel(const int* nbr) {
    int i = blockIdx.x * 256 + threadIdx.x;
    if (i < N_EDGES) atomicAdd(&g_cnt[nbr[2 * i + 1]], 1.f);
}

// ---------------- GEMM1: h1 = silu([x[src],e] @ W1 + b1) ----------------
#define AS_LD 72
#define BS_LD 136

__global__ __launch_bounds__(256) void gemm1_kernel(const int* nbr, const float* conv_b1, int layer) {
    __shared__ __align__(16) __nv_bfloat16 As[128 * AS_LD];
    __shared__ __align__(16) __nv_bfloat16 Bs[64 * BS_LD];
    __shared__ int srcs[128];
    const int tid = threadIdx.x, tile = blockIdx.x, nb = blockIdx.y * 128;
    const __nv_bfloat16* W = g_w1 + layer * H2 * H2;
    if (tid < 128) srcs[tid] = nbr[2 * (tile * 128 + tid)];
    __syncthreads();
    const int wid = tid >> 5, lane = tid & 31, wm = wid & 3, wn = wid >> 2;
    float acc[2][8][4];
    #pragma unroll
    for (int mt = 0; mt < 2; mt++)
        #pragma unroll
        for (int nt = 0; nt < 8; nt++)
            #pragma unroll
            for (int j = 0; j < 4; j++) acc[mt][nt][j] = 0.f;

    for (int kt = 0; kt < 4; kt++) {
        #pragma unroll
        for (int i = 0; i < 4; i++) {
            int idx = i * 256 + tid;
            int row = idx >> 3, c8 = (idx & 7) << 3;
            const __nv_bfloat16* sp = (kt < 2)
                ? (g_x_bf + (size_t)srcs[row] * H + kt * 64 + c8)
                : (g_e_bf + (size_t)(tile * 128 + row) * H + (kt - 2) * 64 + c8);
            *(uint4*)(As + row * AS_LD + c8) = *(const uint4*)sp;
        }
        #pragma unroll
        for (int i = 0; i < 4; i++) {
            int idx = i * 256 + tid;
            int row = idx >> 4, c = (idx & 15) << 3;
            *(uint4*)(Bs + row * BS_LD + c) = *(const uint4*)(W + (kt * 64 + row) * H2 + nb + c);
        }
        __syncthreads();
        #pragma unroll
        for (int k16 = 0; k16 < 4; k16++) {
            uint32_t af[2][4];
            #pragma unroll
            for (int mt = 0; mt < 2; mt++) {
                int r = wm * 32 + mt * 16 + (lane & 15);
                int c = k16 * 16 + ((lane >> 4) << 3);
                ldsm_x4(af[mt], As + r * AS_LD + c);
            }
            uint32_t bfr[4][4];
            #pragma unroll
            for (int q = 0; q < 4; q++) {
                int r = k16 * 16 + (lane & 15);
                int c = wn * 64 + q * 16 + ((lane >> 4) << 3);
                ldsm_x4t(bfr[q], Bs + r * BS_LD + c);
            }
            #pragma unroll
            for (int mt = 0; mt < 2; mt++)
                #pragma unroll
                for (int nt = 0; nt < 8; nt++)
                    mma_bf16(acc[mt][nt], af[mt], bfr[nt >> 1][(nt & 1) * 2], bfr[nt >> 1][(nt & 1) * 2 + 1]);
        }
        __syncthreads();
    }
    const float* bp = conv_b1 + layer * H2;
    #pragma unroll
    for (int mt = 0; mt < 2; mt++) {
        int r0 = tile * 128 + wm * 32 + mt * 16 + (lane >> 2);
        #pragma unroll
        for (int nt = 0; nt < 8; nt++) {
            int col = nb + wn * 64 + nt * 8 + (lane & 3) * 2;
            float b0 = bp[col], b1v = bp[col + 1];
            __nv_bfloat162 v01, v23;
            v01.x = __float2bfloat16(silu(acc[mt][nt][0] + b0));
            v01.y = __float2bfloat16(silu(acc[mt][nt][1] + b1v));
            v23.x = __float2bfloat16(silu(acc[mt][nt][2] + b0));
            v23.y = __float2bfloat16(silu(acc[mt][nt][3] + b1v));
            *(__nv_bfloat162*)(g_h1 + (size_t)r0 * H2 + col) = v01;
            *(__nv_bfloat162*)(g_h1 + (size_t)(r0 + 8) * H2 + col) = v23;
        }
    }
}

// ---------------- GEMM2: aggr[dst] += silu(h1 @ W2 + b2) ----------------
__global__ __launch_bounds__(256) void gemm2_kernel(const int* nbr, const float* conv_b2, int layer) {
    __shared__ __align__(16) __nv_bfloat16 As[128 * AS_LD];
    __shared__ __align__(16) __nv_bfloat16 Bs[64 * BS_LD];
    __shared__ int dsts[128];
    const int tid = threadIdx.x, tile = blockIdx.x;
    const __nv_bfloat16* W = g_w2 + layer * H2 * H;
    if (tid < 128) dsts[tid] = nbr[2 * (tile * 128 + tid) + 1];
    __syncthreads();
    const int wid = tid >> 5, lane = tid & 31, wm = wid & 3, wn = wid >> 2;
    float acc[2][8][4];
    #pragma unroll
    for (int mt = 0; mt < 2; mt++)
        #pragma unroll
        for (int nt = 0; nt < 8; nt++)
            #pragma unroll
            for (int j = 0; j < 4; j++) acc[mt][nt][j] = 0.f;

    for (int kt = 0; kt < 4; kt++) {
        #pragma unroll
        for (int i = 0; i < 4; i++) {
            int idx = i * 256 + tid;
            int row = idx >> 3, c8 = (idx & 7) << 3;
            *(uint4*)(As + row * AS_LD + c8) =
                *(const uint4*)(g_h1 + (size_t)(tile * 128 + row) * H2 + kt * 64 + c8);
        }
        #pragma unroll
        for (int i = 0; i < 4; i++) {
            int idx = i * 256 + tid;
            int row = idx >> 4, c = (idx & 15) << 3;
            *(uint4*)(Bs + row * BS_LD + c) = *(const uint4*)(W + (kt * 64 + row) * H + c);
        }
        __syncthreads();
        #pragma unroll
        for (int k16 = 0; k16 < 4; k16++) {
            uint32_t af[2][4];
            #pragma unroll
            for (int mt = 0; mt < 2; mt++) {
                int r = wm * 32 + mt * 16 + (lane & 15);
                int c = k16 * 16 + ((lane >> 4) << 3);
                ldsm_x4(af[mt], As + r * AS_LD + c);
            }
            uint32_t bfr[4][4];
            #pragma unroll
            for (int q = 0; q < 4; q++) {
                int r = k16 * 16 + (lane & 15);
                int c = wn * 64 + q * 16 + ((lane >> 4) << 3);
                ldsm_x4t(bfr[q], Bs + r * BS_LD + c);
            }
            #pragma unroll
            for (int mt = 0; mt < 2; mt++)
                #pragma unroll
                for (int nt = 0; nt < 8; nt++)
                    mma_bf16(acc[mt][nt], af[mt], bfr[nt >> 1][(nt & 1) * 2], bfr[nt >> 1][(nt & 1) * 2 + 1]);
        }
        __syncthreads();
    }
    const float* bp = conv_b2 + layer * H;
    #pragma unroll
    for (int mt = 0; mt < 2; mt++) {
        int rloc = wm * 32 + mt * 16 + (lane >> 2);
        int d0 = dsts[rloc], d1 = dsts[rloc + 8];
        #pragma unroll
        for (int nt = 0; nt < 8; nt++) {
            int col = wn * 64 + nt * 8 + (lane & 3) * 2;
            float b0 = bp[col], b1v = bp[col + 1];
            float v0 = silu(acc[mt][nt][0] + b0);
            float v1 = silu(acc[mt][nt][1] + b1v);
            float v2 = silu(acc[mt][nt][2] + b0);
            float v3 = silu(acc[mt][nt][3] + b1v);
            red_v2(g_aggr + (size_t)d0 * H + col, v0, v1);
            red_v2(g_aggr + (size_t)d1 * H + col, v2, v3);
        }
    }
}

__global__ __launch_bounds__(H) void update_kernel(const float* lng, const float* lnb, int layer) {
    int n = blockIdx.x, c = threadIdx.x;
    float cnt = g_cnt[n];
    if (cnt < 1.f) cnt = 1.f;
    int idx = n * H + c;
    float v = g_x[idx] + g_aggr[idx] / cnt;
    g_aggr[idx] = 0.f;
    float mean, var;
    ln_stats(v, mean, var);
    float y = (v - mean) * rsqrtf(var + 1e-5f) * lng[layer * H + c] + lnb[layer * H + c];
    g_x[idx] = y;
    g_x_bf[idx] = __float2bfloat16(y);
}

__global__ __launch_bounds__(H) void pool_kernel(const int* bm) {
    int n = blockIdx.x, c = threadIdx.x;
    int g = bm[n];
    atomicAdd(&g_crystal[g * H + c], g_x[n * H + c]);
    if (c == 0) atomicAdd(&g_gcnt[g], 1.f);
}

__global__ __launch_bounds__(H) void head_kernel(const float* w1, const float* b1,
                                                 const float* w2, const float* b2,
                                                 const float* w3, const float* b3, float* out) {
    __shared__ float cr[H], h1s[H], h2s[64];
    int g = blockIdx.x, c = threadIdx.x;
    float gc = g_gcnt[g];
    if (gc < 1.f) gc = 1.f;
    cr[c] = g_crystal[g * H + c] / gc;
    __syncthreads();
    float a = b1[c];
    #pragma unroll 8
    for (int k = 0; k < H; k++) a += cr[k] * w1[k * H + c];
    h1s[c] = silu(a);
    __syncthreads();
    if (c < 64) {
        float a2 = b2[c];
        #pragma unroll 8
        for (int k = 0; k < H; k++) a2 += h1s[k] * w2[k * 64 + c];
        h2s[c] = silu(a2);
    }
    __syncthreads();
    if (c < 3) {
        float a3 = b3[c];
        #pragma unroll
        for (int k = 0; k < 64; k++) a3 += h2s[k] * w3[k * 3 + c];
        out[g * 3 + c] = a3;
    }
}

// ---------------- launch ----------------
extern "C" void kernel_launch(void* const* d_in, const int* in_sizes, int n_in,
                              void* d_out, int out_size) {
    const float* atom_fea   = (const float*)d_in[0];
    const float* nbr_fea    = (const float*)d_in[1];
    const int*   nbr_idx    = (const int*)d_in[2];
    const int*   batch_map  = (const int*)d_in[3];
    const float* emb_w      = (const float*)d_in[4];
    const float* emb_b      = (const float*)d_in[5];
    const float* emb_ln_g   = (const float*)d_in[6];
    const float* emb_ln_b   = (const float*)d_in[7];
    const float* edge_w     = (const float*)d_in[8];
    const float* edge_b     = (const float*)d_in[9];
    const float* conv_w1    = (const float*)d_in[10];
    const float* conv_b1    = (const float*)d_in[11];
    const float* conv_w2    = (const float*)d_in[12];
    const float* conv_b2    = (const float*)d_in[13];
    const float* ln_g       = (const float*)d_in[14];
    const float* ln_b       = (const float*)d_in[15];
    const float* out_w1     = (const float*)d_in[16];
    const float* out_b1     = (const float*)d_in[17];
    const float* out_w2     = (const float*)d_in[18];
    const float* out_b2     = (const float*)d_in[19];
    const float* out_w3     = (const float*)d_in[20];
    const float* out_b3     = (const float*)d_in[21];
    float* out = (float*)d_out;

    zero_kernel<<<(N_NODES * H + 255) / 256, 256>>>();
    prep_w<<<(L * H2 * H2 + 255) / 256, 256>>>(conv_w1, conv_w2);
    node_embed<<<N_NODES, H>>>(atom_fea, emb_w, emb_b, emb_ln_g, emb_ln_b);
    edge_embed<<<N_EDGES / 64, 256>>>(nbr_fea, edge_w, edge_b);
    cnt_kernel<<<(N_EDGES + 255) / 256, 256>>>(nbr_idx);

    for (int l = 0; l < L; l++) {
        gemm1_kernel<<<dim3(N_EDGES / 128, 2), 256>>>(nbr_idx, conv_b1, l);
        gemm2_kernel<<<N_EDGES / 128, 256>>>(nbr_idx, conv_b2, l);
        update_kernel<<<N_NODES, H>>>(ln_g, ln_b, l);
    }

    pool_kernel<<<N_NODES, H>>>(batch_map);
    head_kernel<<<N_GRAPHS, H>>>(out_w1, out_b1, out_w2, out_b2, out_w3, out_b3, out);
}